// round 5
// baseline (speedup 1.0000x reference)
#include <cuda_runtime.h>

#define IMG_H 100
#define IMG_W 100
#define IMG_C 256
#define OUT_HW 7
#define CELLS (OUT_HW * OUT_HW)   // 49

// 256-bit global access (sm_103 native). Image loads via nc path.
__device__ __forceinline__ void ldg256(const float* p, float* v) {
    unsigned r0, r1, r2, r3, r4, r5, r6, r7;
    asm volatile("ld.global.nc.L2::evict_last.v8.b32 {%0,%1,%2,%3,%4,%5,%6,%7}, [%8];"
                 : "=r"(r0), "=r"(r1), "=r"(r2), "=r"(r3),
                   "=r"(r4), "=r"(r5), "=r"(r6), "=r"(r7)
                 : "l"(p));
    v[0] = __uint_as_float(r0); v[1] = __uint_as_float(r1);
    v[2] = __uint_as_float(r2); v[3] = __uint_as_float(r3);
    v[4] = __uint_as_float(r4); v[5] = __uint_as_float(r5);
    v[6] = __uint_as_float(r6); v[7] = __uint_as_float(r7);
}
__device__ __forceinline__ void stg256(float* p, const float* v) {
    asm volatile("st.global.L2::evict_first.v8.b32 [%0], {%1,%2,%3,%4,%5,%6,%7,%8};"
                 :: "l"(p),
                    "r"(__float_as_uint(v[0])), "r"(__float_as_uint(v[1])),
                    "r"(__float_as_uint(v[2])), "r"(__float_as_uint(v[3])),
                    "r"(__float_as_uint(v[4])), "r"(__float_as_uint(v[5])),
                    "r"(__float_as_uint(v[6])), "r"(__float_as_uint(v[7]))
                 : "memory");
}

// One block (256 threads = 8 warps) per roi. roi data loaded ONCE per block,
// then each warp loops over cells w, w+8, ... of the 7x7 grid. Iteration i+1's
// gather addresses depend only on roi registers, so loads of the next cell can
// be hoisted past the current cell's lerp/store (no dependent scalar-load
// epoch per cell anymore).
__global__ void __launch_bounds__(256, 4)
roi_crop_resize_kernel(const float* __restrict__ img,
                       const float* __restrict__ rois,
                       float* __restrict__ out)
{
    int roi  = blockIdx.x;
    int w    = threadIdx.x >> 5;   // warp 0..7
    int lane = threadIdx.x & 31;

    const float* r = rois + roi * 5;
    float rb  = __ldg(r + 0);
    float rx1 = __ldg(r + 1);
    float ry1 = __ldg(r + 2);
    float rx2 = __ldg(r + 3);
    float ry2 = __ldg(r + 4);

    int b = (int)rb;

    // normalized coords exactly as reference: b[:,k] = roi[:,k]/scale
    float x1 = rx1 * (1.0f / IMG_W);
    float x2 = rx2 * (1.0f / IMG_W);
    float y1 = ry1 * (1.0f / IMG_H);
    float y2 = ry2 * (1.0f / IMG_H);

    // in_y = y1*(H-1) + oy * ((y2-y1)*(H-1)/(ch-1))
    float ybase = y1 * (float)(IMG_H - 1);
    float ystep = (y2 - y1) * (float)(IMG_H - 1) / (float)(OUT_HW - 1);
    float xbase = x1 * (float)(IMG_W - 1);
    float xstep = (x2 - x1) * (float)(IMG_W - 1) / (float)(OUT_HW - 1);

    int ch = lane * 8;
    const float* imgb = img + (size_t)b * (IMG_H * IMG_W * IMG_C) + ch;
    float* oroi = out + (size_t)roi * (CELLS * IMG_C) + ch;

    #pragma unroll
    for (int it = 0; it < 7; it++) {
        int c = w + it * 8;
        if (c >= CELLS) break;

        int oy = c / OUT_HW;
        int ox = c - oy * OUT_HW;

        float in_y = ybase + (float)oy * ystep;
        float in_x = xbase + (float)ox * xstep;

        float* ocell = oroi + (size_t)c * IMG_C;

        bool valid = (in_y >= 0.0f) && (in_y <= (float)(IMG_H - 1)) &&
                     (in_x >= 0.0f) && (in_x <= (float)(IMG_W - 1));
        if (!valid) {
            float z[8] = {0.f, 0.f, 0.f, 0.f, 0.f, 0.f, 0.f, 0.f};
            stg256(ocell, z);
            continue;
        }

        float fy = floorf(in_y);
        float fx = floorf(in_x);
        float ly = in_y - fy;
        float lx = in_x - fx;

        int ty = min(max((int)fy, 0), IMG_H - 1);
        int by = min(max((int)ceilf(in_y), 0), IMG_H - 1);
        int tx = min(max((int)fx, 0), IMG_W - 1);
        int bx = min(max((int)ceilf(in_x), 0), IMG_W - 1);

        const float* p_tl = imgb + (size_t)(ty * IMG_W + tx) * IMG_C;
        const float* p_tr = imgb + (size_t)(ty * IMG_W + bx) * IMG_C;
        const float* p_bl = imgb + (size_t)(by * IMG_W + tx) * IMG_C;
        const float* p_br = imgb + (size_t)(by * IMG_W + bx) * IMG_C;

        float tl[8], tr[8], bl[8], br[8];
        ldg256(p_tl, tl);
        ldg256(p_tr, tr);
        ldg256(p_bl, bl);
        ldg256(p_br, br);

        // lerp exactly as reference: top = tl + (tr-tl)*lx; out = top + (bot-top)*ly
        float res[8];
        #pragma unroll
        for (int i = 0; i < 8; i++) {
            float top = tl[i] + (tr[i] - tl[i]) * lx;
            float bot = bl[i] + (br[i] - bl[i]) * lx;
            res[i] = top + (bot - top) * ly;
        }

        stg256(ocell, res);
    }
}

extern "C" void kernel_launch(void* const* d_in, const int* in_sizes, int n_in,
                              void* d_out, int out_size)
{
    const float* img  = (const float*)d_in[0];
    const float* rois = (const float*)d_in[1];
    float* out = (float*)d_out;

    int n_rois = in_sizes[1] / 5;   // 2000

    roi_crop_resize_kernel<<<n_rois, 256>>>(img, rois, out);
}